// round 2
// baseline (speedup 1.0000x reference)
#include <cuda_runtime.h>

// ---------------------------------------------------------------------------
// 2-D elastic staggered-grid FDTD (velocity-stress), persistent kernel with
// neighbor-flag synchronization through L2.
//
// Decomposition: 4 batches x 32 z-tiles of 6 rows -> 128 CTAs, 192 threads
// (one thread per x-column, owning all 6 rows of its column in registers).
// x-derivatives come from SMEM copies (tile spans full x range, no x halo).
// z-halos (one row per phase per direction) are exchanged via __device__
// global buffers guarded by per-CTA release/acquire step counters.
//
// Output layout (matches reference): (NT, NREC, 2*B) with vx in comp 0, vz
// in comp 1:  out[t*NREC*8 + r*8 + comp*4 + b]
// ---------------------------------------------------------------------------

namespace {
constexpr int B_    = 4;
constexpr int NT_   = 256;
constexpr int NZ_   = 192;
constexpr int NX_   = 192;
constexpr int NREC_ = 128;
constexpr int RZ_   = 6;                 // rows per tile
constexpr int NTILES_ = NZ_ / RZ_;       // 32
constexpr int NCTA_   = B_ * NTILES_;    // 128 (< 148 SMs -> all co-resident)
constexpr float DT_ = 0.001f;
constexpr float DH_ = 10.0f;
}

// halo buffers + flags (zeroed by init kernel each launch for graph-replay determinism)
__device__ float g_vz_last [NCTA_][NX_];   // published in phase 1 (vz of last row)
__device__ float g_vx_first[NCTA_][NX_];   // published in phase 1 (vx of first row)
__device__ float g_txz_last[NCTA_][NX_];   // published in phase 2 (txz of last row)
__device__ float g_tzz_first[NCTA_][NX_];  // published in phase 2 (tzz of first row)
__device__ int   g_vflag[NCTA_];
__device__ int   g_sflag[NCTA_];

__device__ __forceinline__ void wait_ge(const int* p, int t) {
    int v;
    do {
        asm volatile("ld.acquire.gpu.global.b32 %0, [%1];" : "=r"(v) : "l"(p));
    } while (v < t);
}
__device__ __forceinline__ void st_release(int* p, int v) {
    asm volatile("st.release.gpu.global.b32 [%0], %1;" :: "l"(p), "r"(v) : "memory");
}
__device__ __forceinline__ float ldcg(const float* p) {
    float v;
    asm volatile("ld.global.cg.f32 %0, [%1];" : "=f"(v) : "l"(p));
    return v;
}

__global__ void init_flags_kernel() {
    int i = blockIdx.x * blockDim.x + threadIdx.x;
    int n = NCTA_ * NX_;
    if (i < n) {
        ((float*)g_vz_last)[i]   = 0.f;
        ((float*)g_vx_first)[i]  = 0.f;
        ((float*)g_txz_last)[i]  = 0.f;
        ((float*)g_tzz_first)[i] = 0.f;
    }
    if (i < NCTA_) { g_vflag[i] = 0; g_sflag[i] = 0; }
}

__global__ void __launch_bounds__(NX_, 1) wave_kernel(
    const float* __restrict__ xsrc,   // (B, NT)
    const float* __restrict__ vp,     // (NZ, NX)
    const float* __restrict__ vs,
    const float* __restrict__ rho,
    const int*   __restrict__ src_loc, // (B, 2)
    const int*   __restrict__ rec_loc, // (NREC, 2)
    float*       __restrict__ out)     // (NT, NREC, 2*B)
{
    const int c  = blockIdx.x;
    const int b  = c / NTILES_;
    const int tz = c % NTILES_;
    const int x  = threadIdx.x;
    const bool has_top = (tz > 0);
    const bool has_bot = (tz < NTILES_ - 1);
    // clamped x-neighbor indices: clamping makes the forward/backward x-diff
    // exactly zero at the domain edge, matching the reference's zero-padding.
    const int xm = (x == 0) ? 0 : x - 1;
    const int xp = (x == NX_ - 1) ? NX_ - 1 : x + 1;

    __shared__ float s_vx [RZ_][NX_];
    __shared__ float s_vz [RZ_][NX_];
    __shared__ float s_txx[RZ_][NX_];
    __shared__ float s_txz[RZ_][NX_];

    // per-cell material coefficients (DT and 1/DH folded in)
    float bc[RZ_], cl2m[RZ_], clam[RZ_], cmu[RZ_];
    #pragma unroll
    for (int r = 0; r < RZ_; ++r) {
        int gi = (tz * RZ_ + r) * NX_ + x;
        float vpv = __ldg(&vp[gi]);
        float vsv = __ldg(&vs[gi]);
        float rh  = __ldg(&rho[gi]);
        float mu  = rh * vsv * vsv;
        float lam = rh * (vpv * vpv - 2.0f * vsv * vsv);
        float l2m = lam + 2.0f * mu;
        bc[r]   = DT_ / (rh * DH_);
        cl2m[r] = (DT_ / DH_) * l2m;
        clam[r] = (DT_ / DH_) * lam;
        cmu[r]  = (DT_ / DH_) * mu;
    }

    // wavefields (register-resident column strips), zero initial conditions
    float vx[RZ_]  = {}, vz[RZ_]  = {};
    float txx[RZ_] = {}, tzz[RZ_] = {}, txz[RZ_] = {};
    #pragma unroll
    for (int r = 0; r < RZ_; ++r) {
        s_vx[r][x] = 0.f; s_vz[r][x] = 0.f; s_txx[r][x] = 0.f; s_txz[r][x] = 0.f;
    }

    // source ownership
    const int ssz = src_loc[2 * b];
    const int ssx = src_loc[2 * b + 1];
    const bool is_src = ((ssz / RZ_) == tz) && (x == ssx);
    const int src_lr  = ssz % RZ_;

    // receiver ownership: thread index doubles as receiver index
    bool is_rec = false;
    int my_lrz = 0, my_rx = 0;
    if (x < NREC_) {
        int rz = rec_loc[2 * x];
        my_rx  = rec_loc[2 * x + 1];
        if ((rz / RZ_) == tz) { is_rec = true; my_lrz = rz % RZ_; }
    }

    __syncthreads();

    for (int t = 1; t <= NT_; ++t) {
        // ------------------ phase 1: velocity update ------------------
        if (has_top) wait_ge(&g_sflag[c - 1], t - 1);
        if (has_bot) wait_ge(&g_sflag[c + 1], t - 1);

        const float txz_zm_h = has_top ? ldcg(&g_txz_last[c - 1][x]) : 0.f;
        const float tzz_zp_h = has_bot ? ldcg(&g_tzz_first[c + 1][x]) : 0.f;

        #pragma unroll
        for (int r = 0; r < RZ_; ++r) {
            float txx_c  = txx[r];
            float txz_c  = txz[r];
            float txx_xp = s_txx[r][xp];             // x+1 neighbor (LDS)
            float txz_xm = s_txz[r][xm];             // x-1 neighbor (LDS)
            // z-neighbors live in this thread's registers except at tile edges;
            // at the global boundary, using own value makes the diff exactly 0
            // (matches reference zero-padding of dzb/dzf).
            float txz_zm = (r > 0) ? txz[r - 1] : (has_top ? txz_zm_h : txz_c);
            float tzz_zp = (r < RZ_ - 1) ? tzz[r + 1] : (has_bot ? tzz_zp_h : tzz[r]);
            vx[r] += bc[r] * ((txx_xp - txx_c) + (txz_c - txz_zm));
            vz[r] += bc[r] * ((txz_c - txz_xm) + (tzz_zp - tzz[r]));
        }
        #pragma unroll
        for (int r = 0; r < RZ_; ++r) { s_vx[r][x] = vx[r]; s_vz[r][x] = vz[r]; }
        g_vz_last[c][x]  = vz[RZ_ - 1];
        g_vx_first[c][x] = vx[0];
        __threadfence();
        __syncthreads();
        if (x == 0) st_release(&g_vflag[c], t);

        // record receivers: out layout (NT, NREC, 2*B), comp-major within 8
        if (is_rec) {
            int base = (t - 1) * (NREC_ * 2 * B_) + x * (2 * B_);
            out[base + b]      = s_vx[my_lrz][my_rx];
            out[base + B_ + b] = s_vz[my_lrz][my_rx];
        }

        // ------------------ phase 2: stress update ------------------
        if (has_top) wait_ge(&g_vflag[c - 1], t);
        if (has_bot) wait_ge(&g_vflag[c + 1], t);

        const float vz_zm_h = has_top ? ldcg(&g_vz_last[c - 1][x]) : 0.f;
        const float vx_zp_h = has_bot ? ldcg(&g_vx_first[c + 1][x]) : 0.f;

        #pragma unroll
        for (int r = 0; r < RZ_; ++r) {
            float vx_c  = vx[r];
            float vz_c  = vz[r];
            float vx_xm = s_vx[r][xm];
            float vz_xp = s_vz[r][xp];
            float vz_zm = (r > 0) ? vz[r - 1] : (has_top ? vz_zm_h : vz_c);
            float vx_zp = (r < RZ_ - 1) ? vx[r + 1] : (has_bot ? vx_zp_h : vx_c);
            float dvx = vx_c - vx_xm;
            float dvz = vz_c - vz_zm;
            txx[r] += cl2m[r] * dvx + clam[r] * dvz;
            tzz[r] += clam[r] * dvx + cl2m[r] * dvz;
            txz[r] += cmu[r] * ((vx_zp - vx_c) + (vz_xp - vz_c));
        }
        if (is_src) {
            float w = __ldg(&xsrc[b * NT_ + (t - 1)]);
            #pragma unroll
            for (int r = 0; r < RZ_; ++r)
                if (r == src_lr) { txx[r] += w; tzz[r] += w; }
        }
        #pragma unroll
        for (int r = 0; r < RZ_; ++r) { s_txx[r][x] = txx[r]; s_txz[r][x] = txz[r]; }
        g_txz_last[c][x]  = txz[RZ_ - 1];
        g_tzz_first[c][x] = tzz[0];
        __threadfence();
        __syncthreads();
        if (x == 0) st_release(&g_sflag[c], t);
    }
}

extern "C" void kernel_launch(void* const* d_in, const int* in_sizes, int n_in,
                              void* d_out, int out_size) {
    const float* x   = (const float*)d_in[0];
    const float* vp  = (const float*)d_in[1];
    const float* vs  = (const float*)d_in[2];
    const float* rho = (const float*)d_in[3];
    const int* src   = (const int*)d_in[4];
    const int* rec   = (const int*)d_in[5];
    float* out = (float*)d_out;

    // re-zero flags/halos so every graph replay starts from identical state
    init_flags_kernel<<<(NCTA_ * NX_ + 255) / 256, 256>>>();
    wave_kernel<<<NCTA_, NX_>>>(x, vp, vs, rho, src, rec, out);
}

// round 3
// speedup vs baseline: 4.8183x; 4.8183x over previous
#include <cuda_runtime.h>

// ---------------------------------------------------------------------------
// 2-D elastic staggered-grid FDTD (velocity-stress), persistent kernel with
// neighbor-flag synchronization through L2.
//
// Decomposition: 4 batches x 32 z-tiles of 6 rows -> 128 CTAs, 192 threads
// (one thread per x-column, owning all 6 rows of its column in registers).
//
// R2 lesson: acquire (STRONG) loads serialize at the LTS per address. Polling
// from all 192 threads on flags packed into one cache line serialized the
// entire chip. Now: exactly ONE lane polls each needed flag (lane 0 = top,
// lane 32 = bottom, concurrent warps), flags live one per 128B line, and
// visibility is broadcast CTA-wide via __syncthreads().
//
// Output layout (matches reference): (NT, NREC, 2*B):
//   out[t*NREC*8 + r*8 + comp*4 + b], comp 0 = vx, comp 1 = vz.
// ---------------------------------------------------------------------------

namespace {
constexpr int B_    = 4;
constexpr int NT_   = 256;
constexpr int NZ_   = 192;
constexpr int NX_   = 192;
constexpr int NREC_ = 128;
constexpr int RZ_   = 6;                 // rows per tile
constexpr int NTILES_ = NZ_ / RZ_;       // 32
constexpr int NCTA_   = B_ * NTILES_;    // 128 (< 148 SMs -> all co-resident)
constexpr int FPAD_   = 32;              // one flag per 128B line
constexpr float DT_ = 0.001f;
constexpr float DH_ = 10.0f;
}

// halo buffers + flags (zeroed by init kernel each launch for graph-replay determinism)
__device__ float g_vz_last  [NCTA_][NX_];  // published in phase 1 (vz of last row)
__device__ float g_vx_first [NCTA_][NX_];  // published in phase 1 (vx of first row)
__device__ float g_txz_last [NCTA_][NX_];  // published in phase 2 (txz of last row)
__device__ float g_tzz_first[NCTA_][NX_];  // published in phase 2 (tzz of first row)
__device__ int   g_vflag[NCTA_][FPAD_];    // padded: one flag per 128B line
__device__ int   g_sflag[NCTA_][FPAD_];

__device__ __forceinline__ void wait_ge_acq(const int* p, int t) {
    int v;
    do {
        asm volatile("ld.acquire.gpu.global.b32 %0, [%1];" : "=r"(v) : "l"(p));
    } while (v < t);
}
__device__ __forceinline__ void st_release(int* p, int v) {
    asm volatile("st.release.gpu.global.b32 [%0], %1;" :: "l"(p), "r"(v) : "memory");
}
__device__ __forceinline__ float ldcg(const float* p) {
    float v;
    asm volatile("ld.global.cg.f32 %0, [%1];" : "=f"(v) : "l"(p));
    return v;
}
__device__ __forceinline__ void stcg(float* p, float v) {
    asm volatile("st.global.cg.f32 [%0], %1;" :: "l"(p), "f"(v) : "memory");
}

__global__ void init_flags_kernel() {
    int i = blockIdx.x * blockDim.x + threadIdx.x;
    int n = NCTA_ * NX_;
    if (i < n) {
        ((float*)g_vz_last)[i]   = 0.f;
        ((float*)g_vx_first)[i]  = 0.f;
        ((float*)g_txz_last)[i]  = 0.f;
        ((float*)g_tzz_first)[i] = 0.f;
    }
    if (i < NCTA_ * FPAD_) {
        ((int*)g_vflag)[i] = 0;
        ((int*)g_sflag)[i] = 0;
    }
}

__global__ void __launch_bounds__(NX_, 1) wave_kernel(
    const float* __restrict__ xsrc,    // (B, NT)
    const float* __restrict__ vp,      // (NZ, NX)
    const float* __restrict__ vs,
    const float* __restrict__ rho,
    const int*   __restrict__ src_loc, // (B, 2)
    const int*   __restrict__ rec_loc, // (NREC, 2)
    float*       __restrict__ out)     // (NT, NREC, 2*B)
{
    const int c  = blockIdx.x;
    const int b  = c / NTILES_;
    const int tz = c % NTILES_;
    const int x  = threadIdx.x;
    const bool has_top = (tz > 0);
    const bool has_bot = (tz < NTILES_ - 1);
    // clamped x-neighbors: makes the forward/backward x-diff exactly zero at
    // the domain edge, matching the reference's zero-padding.
    const int xm = (x == 0) ? 0 : x - 1;
    const int xp = (x == NX_ - 1) ? NX_ - 1 : x + 1;

    __shared__ float s_vx [RZ_][NX_];
    __shared__ float s_vz [RZ_][NX_];
    __shared__ float s_txx[RZ_][NX_];
    __shared__ float s_txz[RZ_][NX_];

    // per-cell material coefficients (DT and 1/DH folded in)
    float bc[RZ_], cl2m[RZ_], clam[RZ_], cmu[RZ_];
    #pragma unroll
    for (int r = 0; r < RZ_; ++r) {
        int gi = (tz * RZ_ + r) * NX_ + x;
        float vpv = __ldg(&vp[gi]);
        float vsv = __ldg(&vs[gi]);
        float rh  = __ldg(&rho[gi]);
        float mu  = rh * vsv * vsv;
        float lam = rh * (vpv * vpv - 2.0f * vsv * vsv);
        float l2m = lam + 2.0f * mu;
        bc[r]   = DT_ / (rh * DH_);
        cl2m[r] = (DT_ / DH_) * l2m;
        clam[r] = (DT_ / DH_) * lam;
        cmu[r]  = (DT_ / DH_) * mu;
    }

    // wavefields (register-resident column strips), zero initial conditions
    float vx[RZ_]  = {}, vz[RZ_]  = {};
    float txx[RZ_] = {}, tzz[RZ_] = {}, txz[RZ_] = {};
    #pragma unroll
    for (int r = 0; r < RZ_; ++r) {
        s_vx[r][x] = 0.f; s_vz[r][x] = 0.f; s_txx[r][x] = 0.f; s_txz[r][x] = 0.f;
    }

    // source ownership
    const int ssz = src_loc[2 * b];
    const int ssx = src_loc[2 * b + 1];
    const bool is_src = ((ssz / RZ_) == tz) && (x == ssx);
    const int src_lr  = ssz % RZ_;

    // receiver ownership: thread index doubles as receiver index
    bool is_rec = false;
    int my_lrz = 0, my_rx = 0;
    if (x < NREC_) {
        int rz = rec_loc[2 * x];
        my_rx  = rec_loc[2 * x + 1];
        if ((rz / RZ_) == tz) { is_rec = true; my_lrz = rz % RZ_; }
    }

    __syncthreads();

    for (int t = 1; t <= NT_; ++t) {
        // ------------------ phase 1: velocity update ------------------
        // exactly one lane per needed flag polls; two pollers sit in
        // different warps so the waits overlap. syncthreads broadcasts.
        if (has_top && x == 0)  wait_ge_acq(&g_sflag[c - 1][0], t - 1);
        if (has_bot && x == 32) wait_ge_acq(&g_sflag[c + 1][0], t - 1);
        __syncthreads();

        const float txz_zm_h = has_top ? ldcg(&g_txz_last[c - 1][x]) : 0.f;
        const float tzz_zp_h = has_bot ? ldcg(&g_tzz_first[c + 1][x]) : 0.f;

        #pragma unroll
        for (int r = 0; r < RZ_; ++r) {
            float txx_c  = txx[r];
            float txz_c  = txz[r];
            float txx_xp = s_txx[r][xp];   // x+1 neighbor (LDS)
            float txz_xm = s_txz[r][xm];   // x-1 neighbor (LDS)
            // z-neighbors in registers except at tile edges; at the global
            // boundary, using own value makes the diff exactly 0.
            float txz_zm = (r > 0) ? txz[r - 1] : (has_top ? txz_zm_h : txz_c);
            float tzz_zp = (r < RZ_ - 1) ? tzz[r + 1] : (has_bot ? tzz_zp_h : tzz[r]);
            vx[r] += bc[r] * ((txx_xp - txx_c) + (txz_c - txz_zm));
            vz[r] += bc[r] * ((txz_c - txz_xm) + (tzz_zp - tzz[r]));
        }
        #pragma unroll
        for (int r = 0; r < RZ_; ++r) { s_vx[r][x] = vx[r]; s_vz[r][x] = vz[r]; }
        stcg(&g_vz_last[c][x],  vz[RZ_ - 1]);
        stcg(&g_vx_first[c][x], vx[0]);
        __syncthreads();
        // release cumulativity through the barrier orders ALL threads' prior
        // stores (including the .cg halo stores) before this flag store.
        if (x == 0) st_release(&g_vflag[c][0], t);

        // record receivers: out layout (NT, NREC, 2*B)
        if (is_rec) {
            int base = (t - 1) * (NREC_ * 2 * B_) + x * (2 * B_);
            out[base + b]      = s_vx[my_lrz][my_rx];
            out[base + B_ + b] = s_vz[my_lrz][my_rx];
        }

        // ------------------ phase 2: stress update ------------------
        if (has_top && x == 0)  wait_ge_acq(&g_vflag[c - 1][0], t);
        if (has_bot && x == 32) wait_ge_acq(&g_vflag[c + 1][0], t);
        __syncthreads();

        const float vz_zm_h = has_top ? ldcg(&g_vz_last[c - 1][x]) : 0.f;
        const float vx_zp_h = has_bot ? ldcg(&g_vx_first[c + 1][x]) : 0.f;

        #pragma unroll
        for (int r = 0; r < RZ_; ++r) {
            float vx_c  = vx[r];
            float vz_c  = vz[r];
            float vx_xm = s_vx[r][xm];
            float vz_xp = s_vz[r][xp];
            float vz_zm = (r > 0) ? vz[r - 1] : (has_top ? vz_zm_h : vz_c);
            float vx_zp = (r < RZ_ - 1) ? vx[r + 1] : (has_bot ? vx_zp_h : vx_c);
            float dvx = vx_c - vx_xm;
            float dvz = vz_c - vz_zm;
            txx[r] += cl2m[r] * dvx + clam[r] * dvz;
            tzz[r] += clam[r] * dvx + cl2m[r] * dvz;
            txz[r] += cmu[r] * ((vx_zp - vx_c) + (vz_xp - vz_c));
        }
        if (is_src) {
            float w = __ldg(&xsrc[b * NT_ + (t - 1)]);
            #pragma unroll
            for (int r = 0; r < RZ_; ++r)
                if (r == src_lr) { txx[r] += w; tzz[r] += w; }
        }
        #pragma unroll
        for (int r = 0; r < RZ_; ++r) { s_txx[r][x] = txx[r]; s_txz[r][x] = txz[r]; }
        stcg(&g_txz_last[c][x],  txz[RZ_ - 1]);
        stcg(&g_tzz_first[c][x], tzz[0]);
        __syncthreads();
        if (x == 0) st_release(&g_sflag[c][0], t);
    }
}

extern "C" void kernel_launch(void* const* d_in, const int* in_sizes, int n_in,
                              void* d_out, int out_size) {
    const float* x   = (const float*)d_in[0];
    const float* vp  = (const float*)d_in[1];
    const float* vs  = (const float*)d_in[2];
    const float* rho = (const float*)d_in[3];
    const int* src   = (const int*)d_in[4];
    const int* rec   = (const int*)d_in[5];
    float* out = (float*)d_out;

    // re-zero flags/halos so every graph replay starts from identical state
    init_flags_kernel<<<(NCTA_ * NX_ + 255) / 256, 256>>>();
    wave_kernel<<<NCTA_, NX_>>>(x, vp, vs, rho, src, rec, out);
}

// round 4
// speedup vs baseline: 8.4489x; 1.7535x over previous
#include <cuda_runtime.h>

// ---------------------------------------------------------------------------
// 2-D elastic staggered-grid FDTD (velocity-stress), persistent kernel.
//
// R3 -> R4: ONE neighbor handshake per timestep instead of two. The stress
// phase's need for fresh neighbor edge velocities is satisfied by computing
// those ghost velocities REDUNDANTLY from (t-1) data that the neighbor
// publishes in a single 7-row message per step:
//   downward (to c+1): {txz, tzz, vz} of my last row
//   upward   (to c-1): {txx, txz, vx, tzz} of my first row
// Parity double-buffering makes producer overwrites race-free with a single
// per-CTA flag (producer enters step t only after neighbors finished t-1,
// i.e. after they consumed the t-2 contents of the buffer it overwrites).
//
// Decomposition: 4 batches x 32 z-tiles of 6 rows -> 128 CTAs (all resident),
// 192 threads = one per x-column; fields in registers, x-neighbor access via
// SMEM. One lane polls per needed flag (lanes 0 / 32, distinct warps).
//
// Output layout (reference): (NT, NREC, 2*B):
//   out[t*NREC*8 + r*8 + comp*4 + b], comp 0 = vx, comp 1 = vz.
// ---------------------------------------------------------------------------

namespace {
constexpr int B_    = 4;
constexpr int NT_   = 256;
constexpr int NZ_   = 192;
constexpr int NX_   = 192;
constexpr int NREC_ = 128;
constexpr int RZ_   = 6;                 // rows per tile
constexpr int NTILES_ = NZ_ / RZ_;       // 32
constexpr int NCTA_   = B_ * NTILES_;    // 128 (< 148 SMs -> all co-resident)
constexpr int FPAD_   = 32;              // one flag per 128B line
constexpr float DT_ = 0.001f;
constexpr float DH_ = 10.0f;
}

// double-buffered halo messages + flags
__device__ float g_dn[2][NCTA_][3][NX_];  // {txz, tzz, vz} of publisher's LAST row
__device__ float g_up[2][NCTA_][4][NX_];  // {txx, txz, vx, tzz} of publisher's FIRST row
__device__ int   g_flag[NCTA_][FPAD_];

__device__ __forceinline__ void wait_ge_acq(const int* p, int t) {
    int v;
    do {
        asm volatile("ld.acquire.gpu.global.b32 %0, [%1];" : "=r"(v) : "l"(p));
    } while (v < t);
}
__device__ __forceinline__ void st_release(int* p, int v) {
    asm volatile("st.release.gpu.global.b32 [%0], %1;" :: "l"(p), "r"(v) : "memory");
}
__device__ __forceinline__ float ldcg(const float* p) {
    float v;
    asm volatile("ld.global.cg.f32 %0, [%1];" : "=f"(v) : "l"(p));
    return v;
}
__device__ __forceinline__ void stcg(float* p, float v) {
    asm volatile("st.global.cg.f32 [%0], %1;" :: "l"(p), "f"(v) : "memory");
}

__global__ void init_flags_kernel() {
    int i = blockIdx.x * blockDim.x + threadIdx.x;
    int ndn = 2 * NCTA_ * 3 * NX_;
    int nup = 2 * NCTA_ * 4 * NX_;
    if (i < ndn) ((float*)g_dn)[i] = 0.f;
    if (i < nup) ((float*)g_up)[i] = 0.f;
    if (i < NCTA_ * FPAD_) ((int*)g_flag)[i] = 0;
}

__global__ void __launch_bounds__(NX_, 1) wave_kernel(
    const float* __restrict__ xsrc,    // (B, NT)
    const float* __restrict__ vp,      // (NZ, NX)
    const float* __restrict__ vs,
    const float* __restrict__ rho,
    const int*   __restrict__ src_loc, // (B, 2)
    const int*   __restrict__ rec_loc, // (NREC, 2)
    float*       __restrict__ out)     // (NT, NREC, 2*B)
{
    const int c  = blockIdx.x;
    const int b  = c / NTILES_;
    const int tz = c % NTILES_;
    const int x  = threadIdx.x;
    const bool has_top = (tz > 0);
    const bool has_bot = (tz < NTILES_ - 1);
    // clamped x-neighbors: forward/backward x-diff exactly zero at domain edge
    const int xm = (x == 0) ? 0 : x - 1;
    const int xp = (x == NX_ - 1) ? NX_ - 1 : x + 1;

    __shared__ float s_vx [RZ_][NX_];
    __shared__ float s_vz [RZ_][NX_];
    __shared__ float s_txx[RZ_][NX_];
    __shared__ float s_txz[RZ_][NX_];

    // per-cell material coefficients (DT and 1/DH folded in)
    float bc[RZ_], cl2m[RZ_], clam[RZ_], cmu[RZ_];
    #pragma unroll
    for (int r = 0; r < RZ_; ++r) {
        int gi = (tz * RZ_ + r) * NX_ + x;
        float vpv = __ldg(&vp[gi]);
        float vsv = __ldg(&vs[gi]);
        float rh  = __ldg(&rho[gi]);
        float mu  = rh * vsv * vsv;
        float lam = rh * (vpv * vpv - 2.0f * vsv * vsv);
        float l2m = lam + 2.0f * mu;
        bc[r]   = DT_ / (rh * DH_);
        cl2m[r] = (DT_ / DH_) * l2m;
        clam[r] = (DT_ / DH_) * lam;
        cmu[r]  = (DT_ / DH_) * mu;
    }
    // ghost-row buoyancy coefficients (rows z0-1 and z1+1), identical
    // arithmetic to the neighbor's own bc for those rows.
    float bg_top = 0.f, bg_bot = 0.f;
    if (has_top) bg_top = DT_ / (__ldg(&rho[(tz * RZ_ - 1) * NX_ + x]) * DH_);
    if (has_bot) bg_bot = DT_ / (__ldg(&rho[(tz * RZ_ + RZ_) * NX_ + x]) * DH_);

    // wavefields (register-resident column strips), zero initial conditions
    float vx[RZ_]  = {}, vz[RZ_]  = {};
    float txx[RZ_] = {}, tzz[RZ_] = {}, txz[RZ_] = {};
    #pragma unroll
    for (int r = 0; r < RZ_; ++r) {
        s_vx[r][x] = 0.f; s_vz[r][x] = 0.f; s_txx[r][x] = 0.f; s_txz[r][x] = 0.f;
    }

    // source ownership
    const int ssz = src_loc[2 * b];
    const int ssx = src_loc[2 * b + 1];
    const bool is_src = ((ssz / RZ_) == tz) && (x == ssx);
    const int src_lr  = ssz % RZ_;

    // receiver ownership: thread index doubles as receiver index
    bool is_rec = false;
    int my_lrz = 0, my_rx = 0;
    if (x < NREC_) {
        int rz = rec_loc[2 * x];
        my_rx  = rec_loc[2 * x + 1];
        if ((rz / RZ_) == tz) { is_rec = true; my_lrz = rz % RZ_; }
    }

    __syncthreads();

    for (int t = 1; t <= NT_; ++t) {
        // ---- single handshake: wait for neighbors' (t-1) messages ----
        if (has_top && x == 0)  wait_ge_acq(&g_flag[c - 1][0], t - 1);
        if (has_bot && x == 32) wait_ge_acq(&g_flag[c + 1][0], t - 1);
        __syncthreads();

        const int pr = (t - 1) & 1;   // parity of (t-1) data
        // halo loads (all independent -> one L2 latency)
        float ht_txz_x = 0.f, ht_txz_xm = 0.f, ht_tzz = 0.f, ht_vz = 0.f;
        if (has_top) {
            const float* dn = &g_dn[pr][c - 1][0][0];
            ht_txz_x  = ldcg(dn + 0 * NX_ + x);
            ht_txz_xm = ldcg(dn + 0 * NX_ + xm);
            ht_tzz    = ldcg(dn + 1 * NX_ + x);
            ht_vz     = ldcg(dn + 2 * NX_ + x);
        }
        float hb_txx_x = 0.f, hb_txx_xp = 0.f, hb_txz = 0.f, hb_vx = 0.f, hb_tzz = 0.f;
        if (has_bot) {
            const float* up = &g_up[pr][c + 1][0][0];
            hb_txx_x  = ldcg(up + 0 * NX_ + x);
            hb_txx_xp = ldcg(up + 0 * NX_ + xp);
            hb_txz    = ldcg(up + 1 * NX_ + x);
            hb_vx     = ldcg(up + 2 * NX_ + x);
            hb_tzz    = ldcg(up + 3 * NX_ + x);
        }

        // ---- redundant ghost velocities (time t) at rows z0-1 / z1+1 ----
        // identical arithmetic to the neighbor's own update of those rows.
        float vz_g = 0.f, vx_g = 0.f;
        if (has_top)
            vz_g = ht_vz + bg_top * ((ht_txz_x - ht_txz_xm) + (tzz[0] - ht_tzz));
        if (has_bot)
            vx_g = hb_vx + bg_bot * ((hb_txx_xp - hb_txx_x) + (hb_txz - txz[RZ_ - 1]));

        // ------------------ phase V: velocity update ------------------
        #pragma unroll
        for (int r = 0; r < RZ_; ++r) {
            float txx_c  = txx[r];
            float txz_c  = txz[r];
            float txx_xp = s_txx[r][xp];
            float txz_xm = s_txz[r][xm];
            float txz_zm = (r > 0) ? txz[r - 1] : (has_top ? ht_txz_x : txz_c);
            float tzz_zp = (r < RZ_ - 1) ? tzz[r + 1] : (has_bot ? hb_tzz : tzz[r]);
            vx[r] += bc[r] * ((txx_xp - txx_c) + (txz_c - txz_zm));
            vz[r] += bc[r] * ((txz_c - txz_xm) + (tzz_zp - tzz[r]));
        }
        #pragma unroll
        for (int r = 0; r < RZ_; ++r) { s_vx[r][x] = vx[r]; s_vz[r][x] = vz[r]; }
        __syncthreads();

        // record receivers: out layout (NT, NREC, 2*B)
        if (is_rec) {
            int base = (t - 1) * (NREC_ * 2 * B_) + x * (2 * B_);
            out[base + b]      = s_vx[my_lrz][my_rx];
            out[base + B_ + b] = s_vz[my_lrz][my_rx];
        }

        // ------------------ phase S: stress update ------------------
        #pragma unroll
        for (int r = 0; r < RZ_; ++r) {
            float vx_c  = vx[r];
            float vz_c  = vz[r];
            float vx_xm = s_vx[r][xm];
            float vz_xp = s_vz[r][xp];
            float vz_zm = (r > 0) ? vz[r - 1] : (has_top ? vz_g : vz_c);
            float vx_zp = (r < RZ_ - 1) ? vx[r + 1] : (has_bot ? vx_g : vx_c);
            float dvx = vx_c - vx_xm;
            float dvz = vz_c - vz_zm;
            txx[r] += cl2m[r] * dvx + clam[r] * dvz;
            tzz[r] += clam[r] * dvx + cl2m[r] * dvz;
            txz[r] += cmu[r] * ((vx_zp - vx_c) + (vz_xp - vz_c));
        }
        if (is_src) {
            float w = __ldg(&xsrc[b * NT_ + (t - 1)]);
            #pragma unroll
            for (int r = 0; r < RZ_; ++r)
                if (r == src_lr) { txx[r] += w; tzz[r] += w; }
        }
        #pragma unroll
        for (int r = 0; r < RZ_; ++r) { s_txx[r][x] = txx[r]; s_txz[r][x] = txz[r]; }

        // ---- publish time-t message (parity t&1) ----
        {
            const int pw = t & 1;
            float* dn = &g_dn[pw][c][0][0];
            stcg(dn + 0 * NX_ + x, txz[RZ_ - 1]);
            stcg(dn + 1 * NX_ + x, tzz[RZ_ - 1]);
            stcg(dn + 2 * NX_ + x, vz[RZ_ - 1]);
            float* up = &g_up[pw][c][0][0];
            stcg(up + 0 * NX_ + x, txx[0]);
            stcg(up + 1 * NX_ + x, txz[0]);
            stcg(up + 2 * NX_ + x, vx[0]);
            stcg(up + 3 * NX_ + x, tzz[0]);
        }
        __syncthreads();
        // release cumulativity through the barrier orders all threads' prior
        // stores (incl. the .cg halo stores) before the flag store.
        if (x == 0) st_release(&g_flag[c][0], t);
    }
}

extern "C" void kernel_launch(void* const* d_in, const int* in_sizes, int n_in,
                              void* d_out, int out_size) {
    const float* x   = (const float*)d_in[0];
    const float* vp  = (const float*)d_in[1];
    const float* vs  = (const float*)d_in[2];
    const float* rho = (const float*)d_in[3];
    const int* src   = (const int*)d_in[4];
    const int* rec   = (const int*)d_in[5];
    float* out = (float*)d_out;

    // re-zero messages/flags so every graph replay starts from identical state
    int n = 2 * NCTA_ * 4 * NX_;
    init_flags_kernel<<<(n + 255) / 256, 256>>>();
    wave_kernel<<<NCTA_, NX_>>>(x, vp, vs, rho, src, rec, out);
}

// round 5
// speedup vs baseline: 12.2590x; 1.4510x over previous
#include <cuda_runtime.h>

// ---------------------------------------------------------------------------
// 2-D elastic staggered-grid FDTD, persistent kernel, k=2 time blocking:
// ONE neighbor handshake per TWO timesteps using 2-row ghost zones.
//
// Per iteration i (steps t1=2i-1, t2=2i) each CTA:
//   - waits for neighbors' iteration (i-1) messages (full t-state apron,
//     rows +/-1 (5 fields) and +/-2 ({3,4} fields)),
//   - redundantly computes ghost t+1 velocities / t+1 edge stresses /
//     t+2 edge velocities (bit-consistent with the neighbor's own math),
//   - runs V1,S1,V2,S2 locally, records receivers at t1 and t2,
//   - publishes its own 2-row apron of the t+2 state (parity buffered).
//
// Source injection is replicated into ghost stresses when the source row
// falls on a ghost row (exercised here: src z=5 is tile 0's last row =
// tile 1's top ghost row).
//
// Output layout (reference): (NT, NREC, 2*B):
//   out[t*NREC*8 + r*8 + comp*4 + b], comp 0 = vx, comp 1 = vz.
// ---------------------------------------------------------------------------

namespace {
constexpr int B_    = 4;
constexpr int NT_   = 256;
constexpr int NZ_   = 192;
constexpr int NX_   = 192;
constexpr int NREC_ = 128;
constexpr int RZ_   = 6;                 // rows per tile
constexpr int NTILES_ = NZ_ / RZ_;       // 32
constexpr int NCTA_   = B_ * NTILES_;    // 128 (< 148 SMs -> all co-resident)
constexpr int FPAD_   = 32;              // one flag per 128B line
constexpr int NIT_    = NT_ / 2;         // 128 iterations
constexpr float DT_ = 0.001f;
constexpr float DH_ = 10.0f;
}

// double-buffered apron messages + flags
// dn (CTA c -> c+1): rows {z1: vx,vz,txx,txz,tzz ; z1-1: vz,txz,tzz}
// up (CTA c -> c-1): rows {z0: vx,vz,txx,txz,tzz ; z0+1: vx,txx,txz,tzz}
__device__ float g_dn[2][NCTA_][8][NX_];
__device__ float g_up[2][NCTA_][9][NX_];
__device__ int   g_flag[NCTA_][FPAD_];

__device__ __forceinline__ void wait_ge_acq(const int* p, int t) {
    int v;
    do {
        asm volatile("ld.acquire.gpu.global.b32 %0, [%1];" : "=r"(v) : "l"(p));
    } while (v < t);
}
__device__ __forceinline__ void st_release(int* p, int v) {
    asm volatile("st.release.gpu.global.b32 [%0], %1;" :: "l"(p), "r"(v) : "memory");
}
__device__ __forceinline__ float ldcg(const float* p) {
    float v;
    asm volatile("ld.global.cg.f32 %0, [%1];" : "=f"(v) : "l"(p));
    return v;
}
__device__ __forceinline__ void stcg(float* p, float v) {
    asm volatile("st.global.cg.f32 [%0], %1;" :: "l"(p), "f"(v) : "memory");
}

__global__ void init_flags_kernel() {
    int i = blockIdx.x * blockDim.x + threadIdx.x;
    if (i < 2 * NCTA_ * 8 * NX_) ((float*)g_dn)[i] = 0.f;
    if (i < 2 * NCTA_ * 9 * NX_) ((float*)g_up)[i] = 0.f;
    if (i < NCTA_ * FPAD_) ((int*)g_flag)[i] = 0;
}

__global__ void __launch_bounds__(NX_, 1) wave_kernel(
    const float* __restrict__ xsrc,    // (B, NT)
    const float* __restrict__ vp,      // (NZ, NX)
    const float* __restrict__ vs,
    const float* __restrict__ rho,
    const int*   __restrict__ src_loc, // (B, 2)
    const int*   __restrict__ rec_loc, // (NREC, 2)
    float*       __restrict__ out)     // (NT, NREC, 2*B)
{
    const int c  = blockIdx.x;
    const int b  = c / NTILES_;
    const int tz = c % NTILES_;
    const int x  = threadIdx.x;
    const bool has_top = (tz > 0);
    const bool has_bot = (tz < NTILES_ - 1);
    const int xm = (x == 0) ? 0 : x - 1;              // clamp -> zero diff at edge
    const int xp = (x == NX_ - 1) ? NX_ - 1 : x + 1;

    __shared__ float s_vx [RZ_][NX_];
    __shared__ float s_vz [RZ_][NX_];
    __shared__ float s_txx[RZ_][NX_];
    __shared__ float s_txz[RZ_][NX_];
    // ghost staging rows (for x-shifted reads of computed ghosts)
    __shared__ float sh_vxa1[NX_], sh_vza1[NX_], sh_txza1[NX_];
    __shared__ float sh_vxp1[NX_], sh_vzp1[NX_], sh_txxp1[NX_];

    // per-cell material coefficients (DT, 1/DH folded in)
    float bc[RZ_], cl2m[RZ_], clam[RZ_], cmu[RZ_];
    #pragma unroll
    for (int r = 0; r < RZ_; ++r) {
        int gi = (tz * RZ_ + r) * NX_ + x;
        float vpv = __ldg(&vp[gi]);
        float vsv = __ldg(&vs[gi]);
        float rh  = __ldg(&rho[gi]);
        float mu  = rh * vsv * vsv;
        float lam = rh * (vpv * vpv - 2.0f * vsv * vsv);
        bc[r]   = DT_ / (rh * DH_);
        cl2m[r] = (DT_ / DH_) * (lam + 2.0f * mu);
        clam[r] = (DT_ / DH_) * lam;
        cmu[r]  = (DT_ / DH_) * mu;
    }
    // ghost-row coefficients: a=z0-1, b=z0-2 (top), p=z1+1, q=z1+2 (bottom)
    float bA=0, bB=0, clamA=0, cl2mA=0, cmuA=0;
    float bP=0, bQ=0, clamP=0, cl2mP=0, cmuP=0;
    if (has_top) {
        int ga = (tz * RZ_ - 1) * NX_ + x;
        int gb = (tz * RZ_ - 2) * NX_ + x;
        float vpv = __ldg(&vp[ga]), vsv = __ldg(&vs[ga]), rh = __ldg(&rho[ga]);
        float mu  = rh * vsv * vsv;
        float lam = rh * (vpv * vpv - 2.0f * vsv * vsv);
        bA = DT_ / (rh * DH_);
        cl2mA = (DT_ / DH_) * (lam + 2.0f * mu);
        clamA = (DT_ / DH_) * lam;
        cmuA  = (DT_ / DH_) * mu;
        bB = DT_ / (__ldg(&rho[gb]) * DH_);
    }
    if (has_bot) {
        int gp = (tz * RZ_ + RZ_) * NX_ + x;
        int gq = (tz * RZ_ + RZ_ + 1) * NX_ + x;
        float vpv = __ldg(&vp[gp]), vsv = __ldg(&vs[gp]), rh = __ldg(&rho[gp]);
        float mu  = rh * vsv * vsv;
        float lam = rh * (vpv * vpv - 2.0f * vsv * vsv);
        bP = DT_ / (rh * DH_);
        cl2mP = (DT_ / DH_) * (lam + 2.0f * mu);
        clamP = (DT_ / DH_) * lam;
        cmuP  = (DT_ / DH_) * mu;
        bQ = DT_ / (__ldg(&rho[gq]) * DH_);
    }

    // wavefields, zero initial conditions
    float vx[RZ_]  = {}, vz[RZ_]  = {};
    float txx[RZ_] = {}, tzz[RZ_] = {}, txz[RZ_] = {};
    #pragma unroll
    for (int r = 0; r < RZ_; ++r) {
        s_vx[r][x] = 0.f; s_vz[r][x] = 0.f; s_txx[r][x] = 0.f; s_txz[r][x] = 0.f;
    }

    // source ownership
    const int ssz = src_loc[2 * b];
    const int ssx = src_loc[2 * b + 1];
    const bool is_src = ((ssz / RZ_) == tz) && (x == ssx);
    const int src_lr  = ssz % RZ_;
    const bool src_at_a = has_top && (ssz == tz * RZ_ - 1)  && (x == ssx);
    const bool src_at_p = has_bot && (ssz == tz * RZ_ + RZ_) && (x == ssx);

    // receiver ownership: thread index doubles as receiver index
    bool is_rec = false;
    int my_lrz = 0, my_rx = 0;
    if (x < NREC_) {
        int rz = rec_loc[2 * x];
        my_rx  = rec_loc[2 * x + 1];
        if ((rz / RZ_) == tz) { is_rec = true; my_lrz = rz % RZ_; }
    }

    __syncthreads();

    for (int i = 1; i <= NIT_; ++i) {
        const int t1 = 2 * i - 1;
        const int t2 = 2 * i;
        const float w1 = __ldg(&xsrc[b * NT_ + (t1 - 1)]);
        const float w2 = __ldg(&xsrc[b * NT_ + (t2 - 1)]);

        // ---- handshake: neighbors' iteration (i-1) aprons ----
        if (has_top && x == 0)  wait_ge_acq(&g_flag[c - 1][0], i - 1);
        if (has_bot && x == 32) wait_ge_acq(&g_flag[c + 1][0], i - 1);
        __syncthreads();

        const int pr = (i - 1) & 1;
        // message loads (rows a=z0-1,b=z0-2 from above; p=z1+1,q=z1+2 below)
        float vxa=0, vza=0, txxa_x=0, txxa_xp=0, txza_x=0, txza_xm=0, tzza=0;
        float vzb=0, txzb_x=0, txzb_xm=0, tzzb=0;
        if (has_top) {
            const float* dn = &g_dn[pr][c - 1][0][0];
            vxa     = ldcg(dn + 0 * NX_ + x);
            vza     = ldcg(dn + 1 * NX_ + x);
            txxa_x  = ldcg(dn + 2 * NX_ + x);
            txxa_xp = ldcg(dn + 2 * NX_ + xp);
            txza_x  = ldcg(dn + 3 * NX_ + x);
            txza_xm = ldcg(dn + 3 * NX_ + xm);
            tzza    = ldcg(dn + 4 * NX_ + x);
            vzb     = ldcg(dn + 5 * NX_ + x);
            txzb_x  = ldcg(dn + 6 * NX_ + x);
            txzb_xm = ldcg(dn + 6 * NX_ + xm);
            tzzb    = ldcg(dn + 7 * NX_ + x);
        }
        float vxp=0, vzp=0, txxp_x=0, txxp_xp=0, txzp_x=0, txzp_xm=0, tzzp=0;
        float vxq=0, txxq_x=0, txxq_xp=0, txzq_x=0, tzzq=0;
        if (has_bot) {
            const float* up = &g_up[pr][c + 1][0][0];
            vxp     = ldcg(up + 0 * NX_ + x);
            vzp     = ldcg(up + 1 * NX_ + x);
            txxp_x  = ldcg(up + 2 * NX_ + x);
            txxp_xp = ldcg(up + 2 * NX_ + xp);
            txzp_x  = ldcg(up + 3 * NX_ + x);
            txzp_xm = ldcg(up + 3 * NX_ + xm);
            tzzp    = ldcg(up + 4 * NX_ + x);
            vxq     = ldcg(up + 5 * NX_ + x);
            txxq_x  = ldcg(up + 6 * NX_ + x);
            txxq_xp = ldcg(up + 6 * NX_ + xp);
            txzq_x  = ldcg(up + 7 * NX_ + x);
            tzzq    = ldcg(up + 8 * NX_ + x);
        }

        // ---- ghost t+1 velocities (pure t-data) ----
        float vza1=0, vzb1=0, vxa1=0, vxp1=0, vxq1=0, vzp1=0;
        if (has_top) {
            vza1 = vza + bA * ((txza_x - txza_xm) + (tzz[0] - tzza));
            vzb1 = vzb + bB * ((txzb_x - txzb_xm) + (tzza - tzzb));
            vxa1 = vxa + bA * ((txxa_xp - txxa_x) + (txza_x - txzb_x));
        }
        if (has_bot) {
            vxp1 = vxp + bP * ((txxp_xp - txxp_x) + (txzp_x - txz[RZ_ - 1]));
            vxq1 = vxq + bQ * ((txxq_xp - txxq_x) + (txzq_x - txzp_x));
            vzp1 = vzp + bP * ((txzp_x - txzp_xm) + (tzzq - tzzp));
        }

        // ------------------ V1 ------------------
        #pragma unroll
        for (int r = 0; r < RZ_; ++r) {
            float txx_c = txx[r], txz_c = txz[r];
            float txz_zm = (r > 0) ? txz[r - 1] : (has_top ? txza_x : txz_c);
            float tzz_zp = (r < RZ_ - 1) ? tzz[r + 1] : (has_bot ? tzzp : tzz[r]);
            vx[r] += bc[r] * ((s_txx[r][xp] - txx_c) + (txz_c - txz_zm));
            vz[r] += bc[r] * ((txz_c - s_txz[r][xm]) + (tzz_zp - tzz[r]));
        }
        #pragma unroll
        for (int r = 0; r < RZ_; ++r) { s_vx[r][x] = vx[r]; s_vz[r][x] = vz[r]; }
        sh_vxa1[x] = vxa1; sh_vza1[x] = vza1;
        sh_vxp1[x] = vxp1; sh_vzp1[x] = vzp1;
        __syncthreads();

        // record t1
        if (is_rec) {
            int base = (t1 - 1) * (NREC_ * 2 * B_) + x * (2 * B_);
            out[base + b]      = s_vx[my_lrz][my_rx];
            out[base + B_ + b] = s_vz[my_lrz][my_rx];
        }

        // ---- ghost t+1 edge stresses ----
        float tzza1=0, txza1=0, txxp1=0, tzzp1=0, txzp1=0;
        if (has_top) {
            tzza1 = tzza + clamA * (vxa1 - sh_vxa1[xm]) + cl2mA * (vza1 - vzb1);
            if (src_at_a) tzza1 += w1;
            txza1 = txza_x + cmuA * ((vx[0] - vxa1) + (sh_vza1[xp] - vza1));
        }
        if (has_bot) {
            float dvx_p = vxp1 - sh_vxp1[xm];
            float dvz_p = vzp1 - vz[RZ_ - 1];
            txxp1 = txxp_x + cl2mP * dvx_p + clamP * dvz_p;
            tzzp1 = tzzp   + clamP * dvx_p + cl2mP * dvz_p;
            if (src_at_p) { txxp1 += w1; tzzp1 += w1; }
            txzp1 = txzp_x + cmuP * ((vxq1 - vxp1) + (sh_vzp1[xp] - vzp1));
        }

        // ------------------ S1 ------------------
        #pragma unroll
        for (int r = 0; r < RZ_; ++r) {
            float vx_c = vx[r], vz_c = vz[r];
            float vz_zm = (r > 0) ? vz[r - 1] : (has_top ? vza1 : vz_c);
            float vx_zp = (r < RZ_ - 1) ? vx[r + 1] : (has_bot ? vxp1 : vx_c);
            float dvx = vx_c - s_vx[r][xm];
            float dvz = vz_c - vz_zm;
            txx[r] += cl2m[r] * dvx + clam[r] * dvz;
            tzz[r] += clam[r] * dvx + cl2m[r] * dvz;
            txz[r] += cmu[r] * ((vx_zp - vx_c) + (s_vz[r][xp] - vz_c));
        }
        if (is_src) {
            #pragma unroll
            for (int r = 0; r < RZ_; ++r)
                if (r == src_lr) { txx[r] += w1; tzz[r] += w1; }
        }
        #pragma unroll
        for (int r = 0; r < RZ_; ++r) { s_txx[r][x] = txx[r]; s_txz[r][x] = txz[r]; }
        sh_txza1[x] = txza1; sh_txxp1[x] = txxp1;
        __syncthreads();

        // ---- ghost t+2 edge velocities ----
        float vza2 = 0, vxp2 = 0;
        if (has_top)
            vza2 = vza1 + bA * ((txza1 - sh_txza1[xm]) + (tzz[0] - tzza1));
        if (has_bot)
            vxp2 = vxp1 + bP * ((sh_txxp1[xp] - txxp1) + (txzp1 - txz[RZ_ - 1]));

        // ------------------ V2 ------------------
        #pragma unroll
        for (int r = 0; r < RZ_; ++r) {
            float txx_c = txx[r], txz_c = txz[r];
            float txz_zm = (r > 0) ? txz[r - 1] : (has_top ? txza1 : txz_c);
            float tzz_zp = (r < RZ_ - 1) ? tzz[r + 1] : (has_bot ? tzzp1 : tzz[r]);
            vx[r] += bc[r] * ((s_txx[r][xp] - txx_c) + (txz_c - txz_zm));
            vz[r] += bc[r] * ((txz_c - s_txz[r][xm]) + (tzz_zp - tzz[r]));
        }
        #pragma unroll
        for (int r = 0; r < RZ_; ++r) { s_vx[r][x] = vx[r]; s_vz[r][x] = vz[r]; }
        __syncthreads();

        // record t2
        if (is_rec) {
            int base = (t2 - 1) * (NREC_ * 2 * B_) + x * (2 * B_);
            out[base + b]      = s_vx[my_lrz][my_rx];
            out[base + B_ + b] = s_vz[my_lrz][my_rx];
        }

        // ------------------ S2 ------------------
        #pragma unroll
        for (int r = 0; r < RZ_; ++r) {
            float vx_c = vx[r], vz_c = vz[r];
            float vz_zm = (r > 0) ? vz[r - 1] : (has_top ? vza2 : vz_c);
            float vx_zp = (r < RZ_ - 1) ? vx[r + 1] : (has_bot ? vxp2 : vx_c);
            float dvx = vx_c - s_vx[r][xm];
            float dvz = vz_c - vz_zm;
            txx[r] += cl2m[r] * dvx + clam[r] * dvz;
            tzz[r] += clam[r] * dvx + cl2m[r] * dvz;
            txz[r] += cmu[r] * ((vx_zp - vx_c) + (s_vz[r][xp] - vz_c));
        }
        if (is_src) {
            #pragma unroll
            for (int r = 0; r < RZ_; ++r)
                if (r == src_lr) { txx[r] += w2; tzz[r] += w2; }
        }
        #pragma unroll
        for (int r = 0; r < RZ_; ++r) { s_txx[r][x] = txx[r]; s_txz[r][x] = txz[r]; }

        // ---- publish t+2 apron (parity i&1) ----
        {
            const int pw = i & 1;
            float* dn = &g_dn[pw][c][0][0];
            stcg(dn + 0 * NX_ + x, vx[RZ_ - 1]);
            stcg(dn + 1 * NX_ + x, vz[RZ_ - 1]);
            stcg(dn + 2 * NX_ + x, txx[RZ_ - 1]);
            stcg(dn + 3 * NX_ + x, txz[RZ_ - 1]);
            stcg(dn + 4 * NX_ + x, tzz[RZ_ - 1]);
            stcg(dn + 5 * NX_ + x, vz[RZ_ - 2]);
            stcg(dn + 6 * NX_ + x, txz[RZ_ - 2]);
            stcg(dn + 7 * NX_ + x, tzz[RZ_ - 2]);
            float* up = &g_up[pw][c][0][0];
            stcg(up + 0 * NX_ + x, vx[0]);
            stcg(up + 1 * NX_ + x, vz[0]);
            stcg(up + 2 * NX_ + x, txx[0]);
            stcg(up + 3 * NX_ + x, txz[0]);
            stcg(up + 4 * NX_ + x, tzz[0]);
            stcg(up + 5 * NX_ + x, vx[1]);
            stcg(up + 6 * NX_ + x, txx[1]);
            stcg(up + 7 * NX_ + x, txz[1]);
            stcg(up + 8 * NX_ + x, tzz[1]);
        }
        __syncthreads();
        // release cumulativity through the barrier orders all threads' prior
        // stores (incl. .cg publishes) before the flag store.
        if (x == 0) st_release(&g_flag[c][0], i);
    }
}

extern "C" void kernel_launch(void* const* d_in, const int* in_sizes, int n_in,
                              void* d_out, int out_size) {
    const float* x   = (const float*)d_in[0];
    const float* vp  = (const float*)d_in[1];
    const float* vs  = (const float*)d_in[2];
    const float* rho = (const float*)d_in[3];
    const int* src   = (const int*)d_in[4];
    const int* rec   = (const int*)d_in[5];
    float* out = (float*)d_out;

    // re-zero messages/flags so every graph replay starts from identical state
    int n = 2 * NCTA_ * 9 * NX_;
    init_flags_kernel<<<(n + 255) / 256, 256>>>();
    wave_kernel<<<NCTA_, NX_>>>(x, vp, vs, rho, src, rec, out);
}

// round 6
// speedup vs baseline: 13.2657x; 1.0821x over previous
#include <cuda_runtime.h>

// ---------------------------------------------------------------------------
// 2-D elastic staggered-grid FDTD, persistent kernel, k=2 time blocking with
// a SOFTWARE-PIPELINED handshake (one handshake per two timesteps).
//
// R5 -> R6 (pure reordering):
//   consumer: V1 interior rows (no message deps) BEFORE polling the flag;
//             message loads issued immediately after sync, with independent
//             SMEM stores overlapping their latency.
//   producer: S2 computes apron rows {0,1,4,5} first, publishes, barriers,
//             releases the flag EARLY, then finishes interior rows {2,3}.
// This shrinks the exposed release->poll->load RTT from both sides.
//
// Everything else (ghost-zone redundant computation, parity double buffer,
// source replication into ghost rows, output layout) as in R5.
// Output layout (reference): (NT, NREC, 2*B):
//   out[t*NREC*8 + r*8 + comp*4 + b], comp 0 = vx, comp 1 = vz.
// ---------------------------------------------------------------------------

namespace {
constexpr int B_    = 4;
constexpr int NT_   = 256;
constexpr int NZ_   = 192;
constexpr int NX_   = 192;
constexpr int NREC_ = 128;
constexpr int RZ_   = 6;                 // rows per tile
constexpr int NTILES_ = NZ_ / RZ_;       // 32
constexpr int NCTA_   = B_ * NTILES_;    // 128 (< 148 SMs -> all co-resident)
constexpr int FPAD_   = 32;              // one flag per 128B line
constexpr int NIT_    = NT_ / 2;         // 128 iterations
constexpr float DT_ = 0.001f;
constexpr float DH_ = 10.0f;
}

// double-buffered apron messages + flags
// dn (CTA c -> c+1): rows {z1: vx,vz,txx,txz,tzz ; z1-1: vz,txz,tzz}
// up (CTA c -> c-1): rows {z0: vx,vz,txx,txz,tzz ; z0+1: vx,txx,txz,tzz}
__device__ float g_dn[2][NCTA_][8][NX_];
__device__ float g_up[2][NCTA_][9][NX_];
__device__ int   g_flag[NCTA_][FPAD_];

__device__ __forceinline__ void wait_ge_acq(const int* p, int t) {
    int v;
    do {
        asm volatile("ld.acquire.gpu.global.b32 %0, [%1];" : "=r"(v) : "l"(p));
    } while (v < t);
}
__device__ __forceinline__ void st_release(int* p, int v) {
    asm volatile("st.release.gpu.global.b32 [%0], %1;" :: "l"(p), "r"(v) : "memory");
}
__device__ __forceinline__ float ldcg(const float* p) {
    float v;
    asm volatile("ld.global.cg.f32 %0, [%1];" : "=f"(v) : "l"(p));
    return v;
}
__device__ __forceinline__ void stcg(float* p, float v) {
    asm volatile("st.global.cg.f32 [%0], %1;" :: "l"(p), "f"(v) : "memory");
}

__global__ void init_flags_kernel() {
    int i = blockIdx.x * blockDim.x + threadIdx.x;
    if (i < 2 * NCTA_ * 8 * NX_) ((float*)g_dn)[i] = 0.f;
    if (i < 2 * NCTA_ * 9 * NX_) ((float*)g_up)[i] = 0.f;
    if (i < NCTA_ * FPAD_) ((int*)g_flag)[i] = 0;
}

__global__ void __launch_bounds__(NX_, 1) wave_kernel(
    const float* __restrict__ xsrc,    // (B, NT)
    const float* __restrict__ vp,      // (NZ, NX)
    const float* __restrict__ vs,
    const float* __restrict__ rho,
    const int*   __restrict__ src_loc, // (B, 2)
    const int*   __restrict__ rec_loc, // (NREC, 2)
    float*       __restrict__ out)     // (NT, NREC, 2*B)
{
    const int c  = blockIdx.x;
    const int b  = c / NTILES_;
    const int tz = c % NTILES_;
    const int x  = threadIdx.x;
    const bool has_top = (tz > 0);
    const bool has_bot = (tz < NTILES_ - 1);
    const int xm = (x == 0) ? 0 : x - 1;              // clamp -> zero diff at edge
    const int xp = (x == NX_ - 1) ? NX_ - 1 : x + 1;

    __shared__ float s_vx [RZ_][NX_];
    __shared__ float s_vz [RZ_][NX_];
    __shared__ float s_txx[RZ_][NX_];
    __shared__ float s_txz[RZ_][NX_];
    // ghost staging rows (for x-shifted reads of computed ghosts)
    __shared__ float sh_vxa1[NX_], sh_vza1[NX_], sh_txza1[NX_];
    __shared__ float sh_vxp1[NX_], sh_vzp1[NX_], sh_txxp1[NX_];

    // per-cell material coefficients (DT, 1/DH folded in)
    float bc[RZ_], cl2m[RZ_], clam[RZ_], cmu[RZ_];
    #pragma unroll
    for (int r = 0; r < RZ_; ++r) {
        int gi = (tz * RZ_ + r) * NX_ + x;
        float vpv = __ldg(&vp[gi]);
        float vsv = __ldg(&vs[gi]);
        float rh  = __ldg(&rho[gi]);
        float mu  = rh * vsv * vsv;
        float lam = rh * (vpv * vpv - 2.0f * vsv * vsv);
        bc[r]   = DT_ / (rh * DH_);
        cl2m[r] = (DT_ / DH_) * (lam + 2.0f * mu);
        clam[r] = (DT_ / DH_) * lam;
        cmu[r]  = (DT_ / DH_) * mu;
    }
    // ghost-row coefficients: a=z0-1, b=z0-2 (top), p=z1+1, q=z1+2 (bottom)
    float bA=0, bB=0, clamA=0, cl2mA=0, cmuA=0;
    float bP=0, bQ=0, clamP=0, cl2mP=0, cmuP=0;
    if (has_top) {
        int ga = (tz * RZ_ - 1) * NX_ + x;
        int gb = (tz * RZ_ - 2) * NX_ + x;
        float vpv = __ldg(&vp[ga]), vsv = __ldg(&vs[ga]), rh = __ldg(&rho[ga]);
        float mu  = rh * vsv * vsv;
        float lam = rh * (vpv * vpv - 2.0f * vsv * vsv);
        bA = DT_ / (rh * DH_);
        cl2mA = (DT_ / DH_) * (lam + 2.0f * mu);
        clamA = (DT_ / DH_) * lam;
        cmuA  = (DT_ / DH_) * mu;
        bB = DT_ / (__ldg(&rho[gb]) * DH_);
    }
    if (has_bot) {
        int gp = (tz * RZ_ + RZ_) * NX_ + x;
        int gq = (tz * RZ_ + RZ_ + 1) * NX_ + x;
        float vpv = __ldg(&vp[gp]), vsv = __ldg(&vs[gp]), rh = __ldg(&rho[gp]);
        float mu  = rh * vsv * vsv;
        float lam = rh * (vpv * vpv - 2.0f * vsv * vsv);
        bP = DT_ / (rh * DH_);
        cl2mP = (DT_ / DH_) * (lam + 2.0f * mu);
        clamP = (DT_ / DH_) * lam;
        cmuP  = (DT_ / DH_) * mu;
        bQ = DT_ / (__ldg(&rho[gq]) * DH_);
    }

    // wavefields, zero initial conditions
    float vx[RZ_]  = {}, vz[RZ_]  = {};
    float txx[RZ_] = {}, tzz[RZ_] = {}, txz[RZ_] = {};
    #pragma unroll
    for (int r = 0; r < RZ_; ++r) {
        s_vx[r][x] = 0.f; s_vz[r][x] = 0.f; s_txx[r][x] = 0.f; s_txz[r][x] = 0.f;
    }

    // source ownership
    const int ssz = src_loc[2 * b];
    const int ssx = src_loc[2 * b + 1];
    const bool is_src = ((ssz / RZ_) == tz) && (x == ssx);
    const int src_lr  = ssz % RZ_;
    const bool src_at_a = has_top && (ssz == tz * RZ_ - 1)  && (x == ssx);
    const bool src_at_p = has_bot && (ssz == tz * RZ_ + RZ_) && (x == ssx);

    // receiver ownership: thread index doubles as receiver index
    bool is_rec = false;
    int my_lrz = 0, my_rx = 0;
    if (x < NREC_) {
        int rz = rec_loc[2 * x];
        my_rx  = rec_loc[2 * x + 1];
        if ((rz / RZ_) == tz) { is_rec = true; my_lrz = rz % RZ_; }
    }

    __syncthreads();

    for (int i = 1; i <= NIT_; ++i) {
        const int t1 = 2 * i - 1;
        const int t2 = 2 * i;
        const float w1 = __ldg(&xsrc[b * NT_ + (t1 - 1)]);
        const float w2 = __ldg(&xsrc[b * NT_ + (t2 - 1)]);

        // ---- V1 interior rows 1..RZ-2 (no message dependence) ----
        #pragma unroll
        for (int r = 1; r < RZ_ - 1; ++r) {
            float txx_c = txx[r], txz_c = txz[r];
            vx[r] += bc[r] * ((s_txx[r][xp] - txx_c) + (txz_c - txz[r - 1]));
            vz[r] += bc[r] * ((txz_c - s_txz[r][xm]) + (tzz[r + 1] - tzz[r]));
        }

        // ---- poll LATE: neighbors' iteration (i-1) aprons ----
        if (has_top && x == 0)  wait_ge_acq(&g_flag[c - 1][0], i - 1);
        if (has_bot && x == 32) wait_ge_acq(&g_flag[c + 1][0], i - 1);
        __syncthreads();   // (1)

        const int pr = (i - 1) & 1;
        // issue all message loads first...
        float vxa=0, vza=0, txxa_x=0, txxa_xp=0, txza_x=0, txza_xm=0, tzza=0;
        float vzb=0, txzb_x=0, txzb_xm=0, tzzb=0;
        if (has_top) {
            const float* dn = &g_dn[pr][c - 1][0][0];
            vxa     = ldcg(dn + 0 * NX_ + x);
            vza     = ldcg(dn + 1 * NX_ + x);
            txxa_x  = ldcg(dn + 2 * NX_ + x);
            txxa_xp = ldcg(dn + 2 * NX_ + xp);
            txza_x  = ldcg(dn + 3 * NX_ + x);
            txza_xm = ldcg(dn + 3 * NX_ + xm);
            tzza    = ldcg(dn + 4 * NX_ + x);
            vzb     = ldcg(dn + 5 * NX_ + x);
            txzb_x  = ldcg(dn + 6 * NX_ + x);
            txzb_xm = ldcg(dn + 6 * NX_ + xm);
            tzzb    = ldcg(dn + 7 * NX_ + x);
        }
        float vxp=0, vzp=0, txxp_x=0, txxp_xp=0, txzp_x=0, txzp_xm=0, tzzp=0;
        float vxq=0, txxq_x=0, txxq_xp=0, txzq_x=0, tzzq=0;
        if (has_bot) {
            const float* up = &g_up[pr][c + 1][0][0];
            vxp     = ldcg(up + 0 * NX_ + x);
            vzp     = ldcg(up + 1 * NX_ + x);
            txxp_x  = ldcg(up + 2 * NX_ + x);
            txxp_xp = ldcg(up + 2 * NX_ + xp);
            txzp_x  = ldcg(up + 3 * NX_ + x);
            txzp_xm = ldcg(up + 3 * NX_ + xm);
            tzzp    = ldcg(up + 4 * NX_ + x);
            vxq     = ldcg(up + 5 * NX_ + x);
            txxq_x  = ldcg(up + 6 * NX_ + x);
            txxq_xp = ldcg(up + 6 * NX_ + xp);
            txzq_x  = ldcg(up + 7 * NX_ + x);
            tzzq    = ldcg(up + 8 * NX_ + x);
        }
        // ...and overlap their latency with independent interior SMEM stores
        #pragma unroll
        for (int r = 1; r < RZ_ - 1; ++r) { s_vx[r][x] = vx[r]; s_vz[r][x] = vz[r]; }

        // ---- ghost t+1 velocities (consume messages) ----
        float vza1=0, vzb1=0, vxa1=0, vxp1=0, vxq1=0, vzp1=0;
        if (has_top) {
            vza1 = vza + bA * ((txza_x - txza_xm) + (tzz[0] - tzza));
            vzb1 = vzb + bB * ((txzb_x - txzb_xm) + (tzza - tzzb));
            vxa1 = vxa + bA * ((txxa_xp - txxa_x) + (txza_x - txzb_x));
        }
        if (has_bot) {
            vxp1 = vxp + bP * ((txxp_xp - txxp_x) + (txzp_x - txz[RZ_ - 1]));
            vxq1 = vxq + bQ * ((txxq_xp - txxq_x) + (txzq_x - txzp_x));
            vzp1 = vzp + bP * ((txzp_x - txzp_xm) + (tzzq - tzzp));
        }

        // ---- V1 edge rows 0 and RZ-1 ----
        {
            float txz_zm = has_top ? txza_x : txz[0];
            vx[0] += bc[0] * ((s_txx[0][xp] - txx[0]) + (txz[0] - txz_zm));
            vz[0] += bc[0] * ((txz[0] - s_txz[0][xm]) + (tzz[1] - tzz[0]));
            constexpr int r = RZ_ - 1;
            float tzz_zp = has_bot ? tzzp : tzz[r];
            vx[r] += bc[r] * ((s_txx[r][xp] - txx[r]) + (txz[r] - txz[r - 1]));
            vz[r] += bc[r] * ((txz[r] - s_txz[r][xm]) + (tzz_zp - tzz[r]));
        }
        s_vx[0][x] = vx[0];             s_vz[0][x] = vz[0];
        s_vx[RZ_ - 1][x] = vx[RZ_ - 1]; s_vz[RZ_ - 1][x] = vz[RZ_ - 1];
        sh_vxa1[x] = vxa1; sh_vza1[x] = vza1;
        sh_vxp1[x] = vxp1; sh_vzp1[x] = vzp1;
        __syncthreads();   // (2)

        // record t1
        if (is_rec) {
            int base = (t1 - 1) * (NREC_ * 2 * B_) + x * (2 * B_);
            out[base + b]      = s_vx[my_lrz][my_rx];
            out[base + B_ + b] = s_vz[my_lrz][my_rx];
        }

        // ---- ghost t+1 edge stresses ----
        float tzza1=0, txza1=0, txxp1=0, tzzp1=0, txzp1=0;
        if (has_top) {
            tzza1 = tzza + clamA * (vxa1 - sh_vxa1[xm]) + cl2mA * (vza1 - vzb1);
            if (src_at_a) tzza1 += w1;
            txza1 = txza_x + cmuA * ((vx[0] - vxa1) + (sh_vza1[xp] - vza1));
        }
        if (has_bot) {
            float dvx_p = vxp1 - sh_vxp1[xm];
            float dvz_p = vzp1 - vz[RZ_ - 1];
            txxp1 = txxp_x + cl2mP * dvx_p + clamP * dvz_p;
            tzzp1 = tzzp   + clamP * dvx_p + cl2mP * dvz_p;
            if (src_at_p) { txxp1 += w1; tzzp1 += w1; }
            txzp1 = txzp_x + cmuP * ((vxq1 - vxp1) + (sh_vzp1[xp] - vzp1));
        }

        // ------------------ S1 ------------------
        #pragma unroll
        for (int r = 0; r < RZ_; ++r) {
            float vx_c = vx[r], vz_c = vz[r];
            float vz_zm = (r > 0) ? vz[r - 1] : (has_top ? vza1 : vz_c);
            float vx_zp = (r < RZ_ - 1) ? vx[r + 1] : (has_bot ? vxp1 : vx_c);
            float dvx = vx_c - s_vx[r][xm];
            float dvz = vz_c - vz_zm;
            txx[r] += cl2m[r] * dvx + clam[r] * dvz;
            tzz[r] += clam[r] * dvx + cl2m[r] * dvz;
            txz[r] += cmu[r] * ((vx_zp - vx_c) + (s_vz[r][xp] - vz_c));
        }
        if (is_src) {
            #pragma unroll
            for (int r = 0; r < RZ_; ++r)
                if (r == src_lr) { txx[r] += w1; tzz[r] += w1; }
        }
        #pragma unroll
        for (int r = 0; r < RZ_; ++r) { s_txx[r][x] = txx[r]; s_txz[r][x] = txz[r]; }
        sh_txza1[x] = txza1; sh_txxp1[x] = txxp1;
        __syncthreads();   // (3)

        // ---- ghost t+2 edge velocities ----
        float vza2 = 0, vxp2 = 0;
        if (has_top)
            vza2 = vza1 + bA * ((txza1 - sh_txza1[xm]) + (tzz[0] - tzza1));
        if (has_bot)
            vxp2 = vxp1 + bP * ((sh_txxp1[xp] - txxp1) + (txzp1 - txz[RZ_ - 1]));

        // ------------------ V2 ------------------
        #pragma unroll
        for (int r = 0; r < RZ_; ++r) {
            float txx_c = txx[r], txz_c = txz[r];
            float txz_zm = (r > 0) ? txz[r - 1] : (has_top ? txza1 : txz_c);
            float tzz_zp = (r < RZ_ - 1) ? tzz[r + 1] : (has_bot ? tzzp1 : tzz[r]);
            vx[r] += bc[r] * ((s_txx[r][xp] - txx_c) + (txz_c - txz_zm));
            vz[r] += bc[r] * ((txz_c - s_txz[r][xm]) + (tzz_zp - tzz[r]));
        }
        #pragma unroll
        for (int r = 0; r < RZ_; ++r) { s_vx[r][x] = vx[r]; s_vz[r][x] = vz[r]; }
        __syncthreads();   // (4)

        // ---- S2 apron rows {0, 1, RZ-2, RZ-1} FIRST, then publish+release ----
        #pragma unroll
        for (int rr = 0; rr < 4; ++rr) {
            const int r = (rr < 2) ? rr : RZ_ - 4 + rr;   // 0,1,RZ-2,RZ-1
            float vx_c = vx[r], vz_c = vz[r];
            float vz_zm = (r > 0) ? vz[r - 1] : (has_top ? vza2 : vz_c);
            float vx_zp = (r < RZ_ - 1) ? vx[r + 1] : (has_bot ? vxp2 : vx_c);
            float dvx = vx_c - s_vx[r][xm];
            float dvz = vz_c - vz_zm;
            txx[r] += cl2m[r] * dvx + clam[r] * dvz;
            tzz[r] += clam[r] * dvx + cl2m[r] * dvz;
            txz[r] += cmu[r] * ((vx_zp - vx_c) + (s_vz[r][xp] - vz_c));
            if (is_src && r == src_lr) { txx[r] += w2; tzz[r] += w2; }
        }
        // publish t+2 apron (parity i&1)
        {
            const int pw = i & 1;
            float* dn = &g_dn[pw][c][0][0];
            stcg(dn + 0 * NX_ + x, vx[RZ_ - 1]);
            stcg(dn + 1 * NX_ + x, vz[RZ_ - 1]);
            stcg(dn + 2 * NX_ + x, txx[RZ_ - 1]);
            stcg(dn + 3 * NX_ + x, txz[RZ_ - 1]);
            stcg(dn + 4 * NX_ + x, tzz[RZ_ - 1]);
            stcg(dn + 5 * NX_ + x, vz[RZ_ - 2]);
            stcg(dn + 6 * NX_ + x, txz[RZ_ - 2]);
            stcg(dn + 7 * NX_ + x, tzz[RZ_ - 2]);
            float* up = &g_up[pw][c][0][0];
            stcg(up + 0 * NX_ + x, vx[0]);
            stcg(up + 1 * NX_ + x, vz[0]);
            stcg(up + 2 * NX_ + x, txx[0]);
            stcg(up + 3 * NX_ + x, txz[0]);
            stcg(up + 4 * NX_ + x, tzz[0]);
            stcg(up + 5 * NX_ + x, vx[1]);
            stcg(up + 6 * NX_ + x, txx[1]);
            stcg(up + 7 * NX_ + x, txz[1]);
            stcg(up + 8 * NX_ + x, tzz[1]);
        }
        __syncthreads();   // (5) — orders all publish stores before release
        if (x == 0) st_release(&g_flag[c][0], i);

        // record t2 (vx/vz final after V2; SMEM valid since sync 4)
        if (is_rec) {
            int base = (t2 - 1) * (NREC_ * 2 * B_) + x * (2 * B_);
            out[base + b]      = s_vx[my_lrz][my_rx];
            out[base + B_ + b] = s_vz[my_lrz][my_rx];
        }

        // ---- S2 interior rows 2..RZ-3 ----
        #pragma unroll
        for (int r = 2; r < RZ_ - 2; ++r) {
            float vx_c = vx[r], vz_c = vz[r];
            float dvx = vx_c - s_vx[r][xm];
            float dvz = vz_c - vz[r - 1];
            txx[r] += cl2m[r] * dvx + clam[r] * dvz;
            tzz[r] += clam[r] * dvx + cl2m[r] * dvz;
            txz[r] += cmu[r] * ((vx[r + 1] - vx_c) + (s_vz[r][xp] - vz_c));
            if (is_src && r == src_lr) { txx[r] += w2; tzz[r] += w2; }
        }
        #pragma unroll
        for (int r = 0; r < RZ_; ++r) { s_txx[r][x] = txx[r]; s_txz[r][x] = txz[r]; }
        __syncthreads();   // (6) — next iter's V1 reads s_txx/s_txz
    }
}

extern "C" void kernel_launch(void* const* d_in, const int* in_sizes, int n_in,
                              void* d_out, int out_size) {
    const float* x   = (const float*)d_in[0];
    const float* vp  = (const float*)d_in[1];
    const float* vs  = (const float*)d_in[2];
    const float* rho = (const float*)d_in[3];
    const int* src   = (const int*)d_in[4];
    const int* rec   = (const int*)d_in[5];
    float* out = (float*)d_out;

    // re-zero messages/flags so every graph replay starts from identical state
    int n = 2 * NCTA_ * 9 * NX_;
    init_flags_kernel<<<(n + 255) / 256, 256>>>();
    wave_kernel<<<NCTA_, NX_>>>(x, vp, vs, rho, src, rec, out);
}